// round 2
// baseline (speedup 1.0000x reference)
#include <cuda_runtime.h>
#include <math.h>

#define L    4096
#define DM   256
#define DI   512
#define DS   16
#define NB   2
#define CL   256      // scan chunk length
#define NCH  16       // number of chunks (NCH*CL == L)

// ---------------- scratch (device globals; no allocation allowed) -------------
__device__ float g_A[DI*DS];          // A = -exp(A_log)
__device__ float g_upwT[512*256];     // up_w transposed to (j=o*4+x*2+y, c)
__device__ float g_xc[NB*DM*L];       // concat(up, skip), (b, 256, 4096)
__device__ float g_xi[NB*DI*L];       // x branch of in_proj, (b, d, l)
__device__ float g_z [NB*DI*L];       // gate branch, (b, d, l)
__device__ float g_u [NB*DI*L];       // silu(conv1d(xi)), (b, d, l)
__device__ float g_dt[NB*DI*L];       // softplus(dt), (b, d, l)
__device__ float g_dbct[NB*48*L];     // dbc transposed, (b, 48, l)
__device__ float g_S [NCH*NB*DI*DS];  // chunk-local final states
__device__ float g_dts[NCH*NB*DI];    // per-chunk dt sums
__device__ float g_H [NCH*NB*DI*DS];  // chunk start states
__device__ float g_yout[NB*DI*L];     // (y + u*D)*silu(z), (b, d, l)
__device__ float g_xr[NB*DM*L];       // xc + mamba_out, (b, 256, 4096)
__device__ float g_y2[NB*128*L];      // conv3x3 output
__device__ float g_mu[128];
__device__ float g_rstd[128];

// ---------------- prep: A = -exp(A_log); transpose up_w ----------------------
__global__ void prep_kernel(const float* __restrict__ Alog,
                            const float* __restrict__ upw) {
    int i = blockIdx.x * 256 + threadIdx.x;
    if (i < 512 * 256) {
        int j = i >> 8, c = i & 255;
        g_upwT[i] = upw[c * 512 + j];
    }
    if (i < DI * DS) g_A[i] = -expf(Alog[i]);
}

// ---------------- generic tiled GEMM: C[m,n] = sum_k A[k,m] * W[n,k] ---------
// MODE 0: upsample (A = x input, W = g_upwT, epilogue scatter + up_b)
// MODE 1: in_proj  (A = g_xc,  epilogue split xi/z)
// MODE 2: x_proj   (A = g_u,   epilogue store dbc transposed)
// MODE 3: dt_proj  (A = g_dbct rows 0..15, epilogue softplus + bias)
// MODE 4: out_proj (A = g_yout, epilogue residual add with g_xc -> g_xr)
template <int MODE>
__global__ void __launch_bounds__(256)
gemm_kernel(const float* __restrict__ Ain, const float* __restrict__ Bw,
            const float* __restrict__ bias, int M, int N, int K, int lda,
            int aStride) {
    const int bz = blockIdx.z;
    const float* A;
    if (MODE == 0)      A = Ain    + (long)bz * aStride;
    else if (MODE == 1) A = g_xc   + (long)bz * aStride;
    else if (MODE == 2) A = g_u    + (long)bz * aStride;
    else if (MODE == 3) A = g_dbct + (long)bz * aStride;
    else                A = g_yout + (long)bz * aStride;
    const float* Bp = (MODE == 0) ? g_upwT : Bw;

    __shared__ float As[16][64];
    __shared__ float Bs[16][64];

    const int tid = threadIdx.x;
    const int m0 = blockIdx.y * 64;
    const int n0 = blockIdx.x * 64;
    const int tm = (tid >> 4) << 2;
    const int tn = (tid & 15) << 2;

    float acc[4][4];
#pragma unroll
    for (int i = 0; i < 4; i++)
#pragma unroll
        for (int j = 0; j < 4; j++) acc[i][j] = 0.f;

    for (int k0 = 0; k0 < K; k0 += 16) {
#pragma unroll
        for (int r = 0; r < 4; r++) {
            int e = tid + (r << 8);
            int kk = e >> 6, mm = e & 63;
            As[kk][mm] = A[(long)(k0 + kk) * lda + m0 + mm];
        }
#pragma unroll
        for (int r = 0; r < 4; r++) {
            int e = tid + (r << 8);
            int nn = e >> 4, kk = e & 15;
            int gn = n0 + nn;
            Bs[kk][nn] = (gn < N) ? Bp[(long)gn * K + k0 + kk] : 0.f;
        }
        __syncthreads();
#pragma unroll
        for (int kk = 0; kk < 16; kk++) {
            float4 av = *reinterpret_cast<const float4*>(&As[kk][tm]);
            float4 bv = *reinterpret_cast<const float4*>(&Bs[kk][tn]);
            float a[4] = {av.x, av.y, av.z, av.w};
            float b[4] = {bv.x, bv.y, bv.z, bv.w};
#pragma unroll
            for (int i = 0; i < 4; i++)
#pragma unroll
                for (int j = 0; j < 4; j++) acc[i][j] = fmaf(a[i], b[j], acc[i][j]);
        }
        __syncthreads();
    }

#pragma unroll
    for (int i = 0; i < 4; i++) {
#pragma unroll
        for (int j = 0; j < 4; j++) {
            int m = m0 + tm + i;
            int n = n0 + tn + j;
            if (n >= N) continue;
            float v = acc[i][j];
            if (MODE == 0) {
                int o = n >> 2, xx = (n >> 1) & 1, yy = n & 1;
                int h = m >> 5, w = m & 31;
                g_xc[((bz * DM + o) << 12) + (((h << 1) + xx) << 6) + ((w << 1) + yy)] =
                    v + bias[o];
            } else if (MODE == 1) {
                if (n < DI) g_xi[((bz * DI + n) << 12) + m] = v;
                else        g_z[((bz * DI + n - DI) << 12) + m] = v;
            } else if (MODE == 2) {
                g_dbct[(bz * 48 + n) * L + m] = v;
            } else if (MODE == 3) {
                float xv = v + bias[n];
                float sp = (xv > 20.f) ? xv : log1pf(__expf(xv));
                g_dt[((bz * DI + n) << 12) + m] = sp;
            } else {
                int off = ((bz * DM + n) << 12) + m;
                g_xr[off] = g_xc[off] + v;
            }
        }
    }
}

// ---------------- skip -> xc channels 128..255 (float4) ----------------------
__global__ void skipcopy_kernel(const float* __restrict__ skip) {
    int i = blockIdx.x * 256 + threadIdx.x;      // float4 index, < NB*128*1024
    if (i >= NB * 128 * 1024) return;
    float4 v = reinterpret_cast<const float4*>(skip)[i];
    int b = i >> 17;
    int c = (i >> 10) & 127;
    int l4 = i & 1023;
    reinterpret_cast<float4*>(g_xc)[((b * 256 + 128 + c) << 10) + l4] = v;
}

// ---------------- depthwise causal conv1d (k=4) + SiLU -----------------------
__global__ void conv1d_kernel(const float* __restrict__ cw,
                              const float* __restrict__ cb) {
    int idx = blockIdx.x * 256 + threadIdx.x;
    if (idx >= NB * DI * L) return;
    int l = idx & (L - 1);
    int bd = idx >> 12;
    int d = bd & (DI - 1);
    int base = bd << 12;
    float s = cb[d];
    const float* w = cw + d * 4;
    if (l >= 3) s = fmaf(g_xi[base + l - 3], w[0], s);
    if (l >= 2) s = fmaf(g_xi[base + l - 2], w[1], s);
    if (l >= 1) s = fmaf(g_xi[base + l - 1], w[2], s);
    s = fmaf(g_xi[base + l], w[3], s);
    g_u[base + l] = s / (1.f + __expf(-s));
}

// ---------------- scan phase A: chunk-local scan (h0 = 0) --------------------
__global__ void __launch_bounds__(128) scanA_kernel() {
    __shared__ float Bs[CL][17];
    const int b = blockIdx.z, c = blockIdx.y;
    const int d = blockIdx.x * 128 + threadIdx.x;
    const int t0 = c * CL;

    for (int i = threadIdx.x; i < DS * CL; i += 128) {
        int n = i >> 8, t = i & 255;
        Bs[t][n] = g_dbct[(b * 48 + 16 + n) * L + t0 + t];
    }
    __syncthreads();

    float Ar[DS];
#pragma unroll
    for (int n = 0; n < DS; n++) Ar[n] = g_A[d * DS + n];
    bool fast = true;
#pragma unroll
    for (int n = 1; n < DS; n++)
        fast = fast && (fabsf(Ar[n] - (n + 1) * Ar[0]) <=
                        4e-6f * fabsf(Ar[n]) + 1e-30f);

    float h[DS];
#pragma unroll
    for (int n = 0; n < DS; n++) h[n] = 0.f;
    float tsum = 0.f;
    const float* dtp = g_dt + ((b * DI + d) << 12) + t0;
    const float* up  = g_u  + ((b * DI + d) << 12) + t0;

    for (int t = 0; t < CL; t++) {
        float dtv = dtp[t], uv = up[t];
        tsum += dtv;
        float du = dtv * uv;
        if (fast) {
            float r = __expf(dtv * Ar[0]);
            float a = r;
#pragma unroll
            for (int n = 0; n < DS; n++) {
                h[n] = fmaf(a, h[n], du * Bs[t][n]);
                a *= r;
            }
        } else {
#pragma unroll
            for (int n = 0; n < DS; n++) {
                float a = __expf(dtv * Ar[n]);
                h[n] = fmaf(a, h[n], du * Bs[t][n]);
            }
        }
    }
    long so = (long)((c * NB + b) * DI + d) * DS;
#pragma unroll
    for (int n = 0; n < DS; n++) g_S[so + n] = h[n];
    g_dts[(c * NB + b) * DI + d] = tsum;
}

// ---------------- scan phase B: combine chunk states (sequential, 16 steps) --
__global__ void scanB_kernel() {
    int id = blockIdx.x * 256 + threadIdx.x;
    if (id >= NB * DI) return;
    int b = id / DI, d = id % DI;
    float Ar[DS];
#pragma unroll
    for (int n = 0; n < DS; n++) Ar[n] = g_A[d * DS + n];
    float h[DS];
#pragma unroll
    for (int n = 0; n < DS; n++) h[n] = 0.f;
    for (int c = 0; c < NCH; c++) {
        long o = (long)((c * NB + b) * DI + d) * DS;
#pragma unroll
        for (int n = 0; n < DS; n++) g_H[o + n] = h[n];
        float ts = g_dts[(c * NB + b) * DI + d];
#pragma unroll
        for (int n = 0; n < DS; n++)
            h[n] = fmaf(__expf(Ar[n] * ts), h[n], g_S[o + n]);
    }
}

// ---------------- scan phase C: full scan w/ start state, fused epilogue -----
__global__ void __launch_bounds__(128) scanC_kernel(const float* __restrict__ Dp) {
    __shared__ float Bs[CL][17];
    __shared__ float Cs[CL][17];
    const int b = blockIdx.z, c = blockIdx.y;
    const int d = blockIdx.x * 128 + threadIdx.x;
    const int t0 = c * CL;

    for (int i = threadIdx.x; i < DS * CL; i += 128) {
        int n = i >> 8, t = i & 255;
        Bs[t][n] = g_dbct[(b * 48 + 16 + n) * L + t0 + t];
        Cs[t][n] = g_dbct[(b * 48 + 32 + n) * L + t0 + t];
    }
    __syncthreads();

    float Ar[DS];
#pragma unroll
    for (int n = 0; n < DS; n++) Ar[n] = g_A[d * DS + n];
    bool fast = true;
#pragma unroll
    for (int n = 1; n < DS; n++)
        fast = fast && (fabsf(Ar[n] - (n + 1) * Ar[0]) <=
                        4e-6f * fabsf(Ar[n]) + 1e-30f);

    float h[DS];
    long ho = (long)((c * NB + b) * DI + d) * DS;
#pragma unroll
    for (int n = 0; n < DS; n++) h[n] = g_H[ho + n];

    const float Dd = Dp[d];
    const int base = ((b * DI + d) << 12) + t0;
    const float* dtp = g_dt + base;
    const float* up  = g_u  + base;
    const float* zp  = g_z  + base;
    float* yo = g_yout + base;

    for (int t = 0; t < CL; t++) {
        float dtv = dtp[t], uv = up[t];
        float du = dtv * uv;
        float y = 0.f;
        if (fast) {
            float r = __expf(dtv * Ar[0]);
            float a = r;
#pragma unroll
            for (int n = 0; n < DS; n++) {
                h[n] = fmaf(a, h[n], du * Bs[t][n]);
                y = fmaf(h[n], Cs[t][n], y);
                a *= r;
            }
        } else {
#pragma unroll
            for (int n = 0; n < DS; n++) {
                float aa = __expf(dtv * Ar[n]);
                h[n] = fmaf(aa, h[n], du * Bs[t][n]);
                y = fmaf(h[n], Cs[t][n], y);
            }
        }
        float zv = zp[t];
        float sz = zv / (1.f + __expf(-zv));
        yo[t] = (y + uv * Dd) * sz;
    }
}

// ---------------- 3x3 conv, pad 1: xr(2,256,64,64) -> y2(2,128,64,64) --------
__global__ void __launch_bounds__(256) conv3_kernel(const float* __restrict__ cw,
                                                    const float* __restrict__ cb) {
    __shared__ float xs[4][34][36];
    __shared__ float ws[8][4][9];
    const int b = blockIdx.z;
    const int o0 = blockIdx.y * 8;
    const int ty0 = (blockIdx.x >> 1) * 32;
    const int tx0 = (blockIdx.x & 1) * 32;
    const int tid = threadIdx.x;
    const int py = (tid >> 4) << 1;   // 0..30
    const int px = (tid & 15) << 1;   // 0..30

    float acc[8][4];
#pragma unroll
    for (int o = 0; o < 8; o++)
#pragma unroll
        for (int p = 0; p < 4; p++) acc[o][p] = 0.f;

    for (int c0 = 0; c0 < 256; c0 += 4) {
        for (int i = tid; i < 4 * 34 * 34; i += 256) {
            int cc = i / (34 * 34);
            int r = (i / 34) % 34;
            int col = i % 34;
            int gy = ty0 - 1 + r, gx = tx0 - 1 + col;
            float v = 0.f;
            if (gy >= 0 && gy < 64 && gx >= 0 && gx < 64)
                v = g_xr[((b * DM + c0 + cc) << 12) + (gy << 6) + gx];
            xs[cc][r][col] = v;
        }
        for (int i = tid; i < 288; i += 256) {
            int o = i / 36, rest = i % 36;
            int cc = rest / 9, k = rest % 9;
            ws[o][cc][k] = cw[((o0 + o) * 256 + c0 + cc) * 9 + k];
        }
        __syncthreads();
#pragma unroll
        for (int cc = 0; cc < 4; cc++) {
            float xv[4][4];
#pragma unroll
            for (int dy = 0; dy < 4; dy++)
#pragma unroll
                for (int dx = 0; dx < 4; dx++)
                    xv[dy][dx] = xs[cc][py + dy][px + dx];
#pragma unroll
            for (int o = 0; o < 8; o++) {
                float w[9];
#pragma unroll
                for (int k = 0; k < 9; k++) w[k] = ws[o][cc][k];
#pragma unroll
                for (int sy = 0; sy < 2; sy++)
#pragma unroll
                    for (int sx = 0; sx < 2; sx++) {
                        float s = acc[o][sy * 2 + sx];
#pragma unroll
                        for (int kh = 0; kh < 3; kh++)
#pragma unroll
                            for (int kw = 0; kw < 3; kw++)
                                s = fmaf(xv[sy + kh][sx + kw], w[kh * 3 + kw], s);
                        acc[o][sy * 2 + sx] = s;
                    }
            }
        }
        __syncthreads();
    }
#pragma unroll
    for (int o = 0; o < 8; o++) {
        float bv = cb[o0 + o];
#pragma unroll
        for (int sy = 0; sy < 2; sy++)
#pragma unroll
            for (int sx = 0; sx < 2; sx++)
                g_y2[((b * 128 + o0 + o) << 12) + ((ty0 + py + sy) << 6) +
                     tx0 + px + sx] = acc[o][sy * 2 + sx] + bv;
    }
}

// ---------------- BN statistics per channel ----------------------------------
__global__ void bnstat_kernel() {
    __shared__ float ss[256], ss2[256];
    int ch = blockIdx.x;
    float s = 0.f, s2 = 0.f;
    for (int i = threadIdx.x; i < NB * L; i += 256) {
        int b = i >> 12, p = i & 4095;
        float v = g_y2[((b * 128 + ch) << 12) + p];
        s += v;
        s2 += v * v;
    }
    ss[threadIdx.x] = s;
    ss2[threadIdx.x] = s2;
    __syncthreads();
    for (int st = 128; st > 0; st >>= 1) {
        if (threadIdx.x < st) {
            ss[threadIdx.x] += ss[threadIdx.x + st];
            ss2[threadIdx.x] += ss2[threadIdx.x + st];
        }
        __syncthreads();
    }
    if (threadIdx.x == 0) {
        float inv = 1.f / (NB * L);
        float mean = ss[0] * inv;
        float var = ss2[0] * inv - mean * mean;
        g_mu[ch] = mean;
        g_rstd[ch] = rsqrtf(var + 1e-5f);
    }
}

// ---------------- BN apply + exact GELU --------------------------------------
__global__ void bngelu_kernel(const float* __restrict__ gamma,
                              const float* __restrict__ beta,
                              float* __restrict__ out) {
    int idx = blockIdx.x * 256 + threadIdx.x;
    if (idx >= NB * 128 * L) return;
    int ch = (idx >> 12) & 127;
    float v = (g_y2[idx] - g_mu[ch]) * g_rstd[ch] * gamma[ch] + beta[ch];
    out[idx] = 0.5f * v * (1.f + erff(v * 0.70710678118654752f));
}

// ---------------- launch ------------------------------------------------------
extern "C" void kernel_launch(void* const* d_in, const int* in_sizes, int n_in,
                              void* d_out, int out_size) {
    const float* x        = (const float*)d_in[0];
    const float* skip     = (const float*)d_in[1];
    const float* up_w     = (const float*)d_in[2];
    const float* up_b     = (const float*)d_in[3];
    const float* in_proj  = (const float*)d_in[4];
    const float* conv1d_w = (const float*)d_in[5];
    const float* conv1d_b = (const float*)d_in[6];
    const float* x_proj   = (const float*)d_in[7];
    const float* dt_proj  = (const float*)d_in[8];
    const float* dt_b     = (const float*)d_in[9];
    const float* A_log    = (const float*)d_in[10];
    const float* Dp       = (const float*)d_in[11];
    const float* out_proj = (const float*)d_in[12];
    const float* conv_w   = (const float*)d_in[13];
    const float* conv_b   = (const float*)d_in[14];
    const float* bn_g     = (const float*)d_in[15];
    const float* bn_b     = (const float*)d_in[16];
    float* out = (float*)d_out;

    prep_kernel<<<512, 256>>>(A_log, up_w);

    // upsample GEMM: M=1024, N=512, K=256 per batch
    gemm_kernel<0><<<dim3(8, 16, NB), 256>>>(x, nullptr, up_b, 1024, 512, 256,
                                             1024, 256 * 1024);
    skipcopy_kernel<<<1024, 256>>>(skip);

    // in_proj: M=4096, N=1024, K=256
    gemm_kernel<1><<<dim3(16, 64, NB), 256>>>(nullptr, in_proj, nullptr, L, 1024,
                                              256, L, DM * L);
    conv1d_kernel<<<(NB * DI * L) / 256, 256>>>(conv1d_w, conv1d_b);

    // x_proj: M=4096, N=48, K=512
    gemm_kernel<2><<<dim3(1, 64, NB), 256>>>(nullptr, x_proj, nullptr, L, 48, DI,
                                             L, DI * L);
    // dt_proj: M=4096, N=512, K=16
    gemm_kernel<3><<<dim3(8, 64, NB), 256>>>(nullptr, dt_proj, dt_b, L, DI, 16,
                                             L, 48 * L);

    scanA_kernel<<<dim3(4, NCH, NB), 128>>>();
    scanB_kernel<<<4, 256>>>();
    scanC_kernel<<<dim3(4, NCH, NB), 128>>>(Dp);

    // out_proj (+residual): M=4096, N=256, K=512
    gemm_kernel<4><<<dim3(4, 64, NB), 256>>>(nullptr, out_proj, nullptr, L, DM,
                                             DI, L, DI * L);

    conv3_kernel<<<dim3(4, 16, NB), 256>>>(conv_w, conv_b);
    bnstat_kernel<<<128, 256>>>();
    bngelu_kernel<<<(NB * 128 * L) / 256, 256>>>(bn_g, bn_b, out);
}

// round 3
// speedup vs baseline: 1.4019x; 1.4019x over previous
#include <cuda_runtime.h>
#include <math.h>

#define L    4096
#define DM   256
#define DI   512
#define DS   16
#define NB   2
#define CL   128      // scan chunk length
#define NCH  32       // number of chunks (NCH*CL == L)

// ---------------- scratch (device globals) -----------------------------------
__device__ float g_A[DI*DS];
__device__ float g_upwT[512*256];
__device__ float g_xc[NB*DM*L];
__device__ float g_xi[NB*DI*L];
__device__ float g_z [NB*DI*L];
__device__ float g_u [NB*DI*L];
__device__ float g_dt[NB*DI*L];
__device__ float g_dbct[NB*48*L];
__device__ float g_S [NCH*NB*DI*DS];
__device__ float g_dts[NCH*NB*DI];
__device__ float g_H [NCH*NB*DI*DS];
__device__ float g_yout[NB*DI*L];
__device__ float g_xr[NB*DM*L];
__device__ float g_y2s[2][NB*128*L];   // conv3 partial sums (cin split in 2)
__device__ float g_mu[128];
__device__ float g_rstd[128];

// ---------------- prep -------------------------------------------------------
__global__ void prep_kernel(const float* __restrict__ Alog,
                            const float* __restrict__ upw) {
    int i = blockIdx.x * 256 + threadIdx.x;
    if (i < 512 * 256) {
        int j = i >> 8, c = i & 255;
        g_upwT[i] = upw[c * 512 + j];
    }
    if (i < DI * DS) g_A[i] = -expf(Alog[i]);
}

// ---------------- GEMM: C[m,n] = sum_k A[k*lda+m] * W[n*K+k] -----------------
// 128(m) x 64(n) tile, 256 threads, 8x4 per thread, double-buffered smem.
// MODE 0: upsample (scatter epilogue + up_b)
// MODE 1: in_proj  (split xi/z, coalesced)
// MODE 2: x_proj   (store dbc transposed, N=48 guard)
// MODE 3: dt_proj  (softplus + bias)
// MODE 4: out_proj (residual add with g_xc -> g_xr)
template <int MODE>
__global__ void __launch_bounds__(256)
gemm_kernel(const float* __restrict__ Ain, const float* __restrict__ Bw,
            const float* __restrict__ bias, int N, int K, int lda, int aStride) {
    const int bz = blockIdx.z;
    const float* A;
    if (MODE == 0)      A = Ain    + (long)bz * aStride;
    else if (MODE == 1) A = g_xc   + (long)bz * aStride;
    else if (MODE == 2) A = g_u    + (long)bz * aStride;
    else if (MODE == 3) A = g_dbct + (long)bz * aStride;
    else                A = g_yout + (long)bz * aStride;
    const float* Bp = (MODE == 0) ? g_upwT : Bw;

    __shared__ float sm[6144];   // As[2][16][128] | Bs[2][16][64]; reused as Es
#define AS(buf,k,m) sm[(buf)*2048 + (k)*128 + (m)]
#define BS(buf,k,n) sm[4096 + (buf)*1024 + (k)*64 + (n)]
#define ES(n,m)     sm[(n)*132 + (m)]

    const int tid = threadIdx.x;
    const int m0 = blockIdx.y * 128;
    const int n0 = blockIdx.x * 64;
    const int tm = (tid >> 4) << 3;   // 0..120
    const int tn = (tid & 15) << 2;   // 0..60

    // loader indices
    const int lak = tid >> 5;            // A rows 0..7 (and +8)
    const int lam = (tid & 31) << 2;     // A col (m) 0..124
    const int lbn = tid & 63;            // B n
    const int lbk = (tid >> 6) << 2;     // B k group 0,4,8,12
    const int gbn = n0 + lbn;

    float acc[8][4];
#pragma unroll
    for (int i = 0; i < 8; i++)
#pragma unroll
        for (int j = 0; j < 4; j++) acc[i][j] = 0.f;

    const int nk = K >> 4;

    // preload tile 0
    {
        float4 a0 = *(const float4*)(A + (long)lak * lda + m0 + lam);
        float4 a1 = *(const float4*)(A + (long)(lak + 8) * lda + m0 + lam);
        float4 b0 = make_float4(0.f, 0.f, 0.f, 0.f);
        if (gbn < N) b0 = *(const float4*)(Bp + (long)gbn * K + lbk);
        *(float4*)&AS(0, lak, lam) = a0;
        *(float4*)&AS(0, lak + 8, lam) = a1;
        BS(0, lbk + 0, lbn) = b0.x;
        BS(0, lbk + 1, lbn) = b0.y;
        BS(0, lbk + 2, lbn) = b0.z;
        BS(0, lbk + 3, lbn) = b0.w;
    }
    __syncthreads();

    for (int kt = 0; kt < nk; kt++) {
        const int cur = kt & 1;
        float4 na0, na1, nb;
        if (kt + 1 < nk) {
            int k0 = (kt + 1) << 4;
            na0 = *(const float4*)(A + (long)(k0 + lak) * lda + m0 + lam);
            na1 = *(const float4*)(A + (long)(k0 + lak + 8) * lda + m0 + lam);
            nb = make_float4(0.f, 0.f, 0.f, 0.f);
            if (gbn < N) nb = *(const float4*)(Bp + (long)gbn * K + k0 + lbk);
        }
#pragma unroll
        for (int kk = 0; kk < 16; kk++) {
            float4 av0 = *(float4*)&AS(cur, kk, tm);
            float4 av1 = *(float4*)&AS(cur, kk, tm + 4);
            float4 bv = *(float4*)&BS(cur, kk, tn);
            float a[8] = {av0.x, av0.y, av0.z, av0.w, av1.x, av1.y, av1.z, av1.w};
            float b[4] = {bv.x, bv.y, bv.z, bv.w};
#pragma unroll
            for (int i = 0; i < 8; i++)
#pragma unroll
                for (int j = 0; j < 4; j++)
                    acc[i][j] = fmaf(a[i], b[j], acc[i][j]);
        }
        if (kt + 1 < nk) {
            int nxt = cur ^ 1;
            *(float4*)&AS(nxt, lak, lam) = na0;
            *(float4*)&AS(nxt, lak + 8, lam) = na1;
            BS(nxt, lbk + 0, lbn) = nb.x;
            BS(nxt, lbk + 1, lbn) = nb.y;
            BS(nxt, lbk + 2, lbn) = nb.z;
            BS(nxt, lbk + 3, lbn) = nb.w;
        }
        __syncthreads();
    }

    if (MODE == 0) {
        // scatter epilogue: n -> (o,x,y), m -> (h,w); write up + bias into g_xc
#pragma unroll
        for (int i = 0; i < 8; i++) {
#pragma unroll
            for (int j = 0; j < 4; j++) {
                int m = m0 + tm + i;
                int n = n0 + tn + j;
                int o = n >> 2, xx = (n >> 1) & 1, yy = n & 1;
                int h = m >> 5, w = m & 31;
                g_xc[((bz * DM + o) << 12) + (((h << 1) + xx) << 6) +
                     ((w << 1) + yy)] = acc[i][j] + bias[o];
            }
        }
        return;
    }

    // smem-staged transposed epilogue (coalesced stores along m)
    for (int half = 0; half < 2; half++) {
        __syncthreads();
        if ((tn >> 5) == half) {
#pragma unroll
            for (int j = 0; j < 4; j++)
#pragma unroll
                for (int i = 0; i < 8; i++)
                    ES((tn & 31) + j, tm + i) = acc[i][j];
        }
        __syncthreads();
        int n = tid >> 3;             // 0..31
        int seg = (tid & 7) << 4;     // m offset, 16 floats
        int gn = n0 + half * 32 + n;
        if (MODE == 2 && gn >= N) continue;
        int gm = m0 + seg;
        if (MODE == 1) {
            float* dst = (gn < DI) ? (g_xi + (((bz * DI + gn) << 12) + gm))
                                   : (g_z + (((bz * DI + (gn - DI)) << 12) + gm));
#pragma unroll
            for (int q = 0; q < 4; q++)
                ((float4*)dst)[q] = *(float4*)&ES(n, seg + (q << 2));
        } else if (MODE == 2) {
            float* dst = g_dbct + (bz * 48 + gn) * L + gm;
#pragma unroll
            for (int q = 0; q < 4; q++)
                ((float4*)dst)[q] = *(float4*)&ES(n, seg + (q << 2));
        } else if (MODE == 3) {
            float bn = bias[gn];
            float* dst = g_dt + ((bz * DI + gn) << 12) + gm;
#pragma unroll
            for (int q = 0; q < 4; q++) {
                float4 v = *(float4*)&ES(n, seg + (q << 2));
                float4 r;
                float t;
                t = v.x + bn; r.x = (t > 20.f) ? t : log1pf(__expf(t));
                t = v.y + bn; r.y = (t > 20.f) ? t : log1pf(__expf(t));
                t = v.z + bn; r.z = (t > 20.f) ? t : log1pf(__expf(t));
                t = v.w + bn; r.w = (t > 20.f) ? t : log1pf(__expf(t));
                ((float4*)dst)[q] = r;
            }
        } else {  // MODE 4
            const float* src = g_xc + ((bz * DM + gn) << 12) + gm;
            float* dst = g_xr + ((bz * DM + gn) << 12) + gm;
#pragma unroll
            for (int q = 0; q < 4; q++) {
                float4 v = *(float4*)&ES(n, seg + (q << 2));
                float4 c = ((const float4*)src)[q];
                v.x += c.x; v.y += c.y; v.z += c.z; v.w += c.w;
                ((float4*)dst)[q] = v;
            }
        }
    }
#undef AS
#undef BS
#undef ES
}

// ---------------- skip -> xc channels 128..255 -------------------------------
__global__ void skipcopy_kernel(const float* __restrict__ skip) {
    int i = blockIdx.x * 256 + threadIdx.x;
    if (i >= NB * 128 * 1024) return;
    float4 v = reinterpret_cast<const float4*>(skip)[i];
    int b = i >> 17;
    int c = (i >> 10) & 127;
    int l4 = i & 1023;
    reinterpret_cast<float4*>(g_xc)[((b * 256 + 128 + c) << 10) + l4] = v;
}

// ---------------- depthwise causal conv1d (k=4) + SiLU, float4 ---------------
__global__ void conv1d_kernel(const float* __restrict__ cw,
                              const float* __restrict__ cb) {
    int i4 = blockIdx.x * 256 + threadIdx.x;
    if (i4 >= NB * DI * (L / 4)) return;
    int l4 = i4 & 1023;
    int bd = i4 >> 10;
    int d = bd & (DI - 1);
    const float4* src = (const float4*)(g_xi + ((long)bd << 12));
    float4 c = src[l4];
    float4 p = (l4 > 0) ? src[l4 - 1] : make_float4(0.f, 0.f, 0.f, 0.f);
    float w0 = cw[d * 4], w1 = cw[d * 4 + 1], w2 = cw[d * 4 + 2], w3 = cw[d * 4 + 3];
    float bb = cb[d];
    float4 o;
    o.x = fmaf(p.y, w0, fmaf(p.z, w1, fmaf(p.w, w2, fmaf(c.x, w3, bb))));
    o.y = fmaf(p.z, w0, fmaf(p.w, w1, fmaf(c.x, w2, fmaf(c.y, w3, bb))));
    o.z = fmaf(p.w, w0, fmaf(c.x, w1, fmaf(c.y, w2, fmaf(c.z, w3, bb))));
    o.w = fmaf(c.x, w0, fmaf(c.y, w1, fmaf(c.z, w2, fmaf(c.w, w3, bb))));
    o.x = o.x / (1.f + __expf(-o.x));
    o.y = o.y / (1.f + __expf(-o.y));
    o.z = o.z / (1.f + __expf(-o.z));
    o.w = o.w / (1.f + __expf(-o.w));
    ((float4*)(g_u + ((long)bd << 12)))[l4] = o;
}

// ---------------- scan phase A: chunk-local scan (h0 = 0) --------------------
__global__ void __launch_bounds__(128) scanA_kernel() {
    __shared__ float Bs[CL][17];
    const int b = blockIdx.z, c = blockIdx.y;
    const int d = blockIdx.x * 128 + threadIdx.x;
    const int t0 = c * CL;

    for (int i = threadIdx.x; i < DS * CL; i += 128) {
        int n = i >> 7, t = i & (CL - 1);
        Bs[t][n] = g_dbct[(b * 48 + 16 + n) * L + t0 + t];
    }
    __syncthreads();

    float Ar[DS];
#pragma unroll
    for (int n = 0; n < DS; n++) Ar[n] = g_A[d * DS + n];
    bool fast = true;
#pragma unroll
    for (int n = 1; n < DS; n++)
        fast = fast && (fabsf(Ar[n] - (n + 1) * Ar[0]) <=
                        4e-6f * fabsf(Ar[n]) + 1e-30f);

    float h[DS];
#pragma unroll
    for (int n = 0; n < DS; n++) h[n] = 0.f;
    float tsum = 0.f;
    const float* dtp = g_dt + ((b * DI + d) << 12) + t0;
    const float* up  = g_u  + ((b * DI + d) << 12) + t0;

    for (int t = 0; t < CL; t++) {
        float dtv = dtp[t], uv = up[t];
        tsum += dtv;
        float du = dtv * uv;
        if (fast) {
            float r = __expf(dtv * Ar[0]);
            float a = r;
#pragma unroll
            for (int n = 0; n < DS; n++) {
                h[n] = fmaf(a, h[n], du * Bs[t][n]);
                a *= r;
            }
        } else {
#pragma unroll
            for (int n = 0; n < DS; n++) {
                float a = __expf(dtv * Ar[n]);
                h[n] = fmaf(a, h[n], du * Bs[t][n]);
            }
        }
    }
    long so = (long)((c * NB + b) * DI + d) * DS;
#pragma unroll
    for (int n = 0; n < DS; n++) g_S[so + n] = h[n];
    g_dts[(c * NB + b) * DI + d] = tsum;
}

// ---------------- scan phase B: combine chunk states -------------------------
__global__ void scanB_kernel() {
    int id = blockIdx.x * 256 + threadIdx.x;
    if (id >= NB * DI) return;
    int b = id / DI, d = id % DI;
    float Ar[DS];
#pragma unroll
    for (int n = 0; n < DS; n++) Ar[n] = g_A[d * DS + n];
    float h[DS];
#pragma unroll
    for (int n = 0; n < DS; n++) h[n] = 0.f;
    for (int c = 0; c < NCH; c++) {
        long o = (long)((c * NB + b) * DI + d) * DS;
#pragma unroll
        for (int n = 0; n < DS; n++) g_H[o + n] = h[n];
        float ts = g_dts[(c * NB + b) * DI + d];
#pragma unroll
        for (int n = 0; n < DS; n++)
            h[n] = fmaf(__expf(Ar[n] * ts), h[n], g_S[o + n]);
    }
}

// ---------------- scan phase C: full scan w/ start state + fused epilogue ----
__global__ void __launch_bounds__(128) scanC_kernel(const float* __restrict__ Dp) {
    __shared__ float Bs[CL][17];
    __shared__ float Cs[CL][17];
    const int b = blockIdx.z, c = blockIdx.y;
    const int d = blockIdx.x * 128 + threadIdx.x;
    const int t0 = c * CL;

    for (int i = threadIdx.x; i < DS * CL; i += 128) {
        int n = i >> 7, t = i & (CL - 1);
        Bs[t][n] = g_dbct[(b * 48 + 16 + n) * L + t0 + t];
        Cs[t][n] = g_dbct[(b * 48 + 32 + n) * L + t0 + t];
    }
    __syncthreads();

    float Ar[DS];
#pragma unroll
    for (int n = 0; n < DS; n++) Ar[n] = g_A[d * DS + n];
    bool fast = true;
#pragma unroll
    for (int n = 1; n < DS; n++)
        fast = fast && (fabsf(Ar[n] - (n + 1) * Ar[0]) <=
                        4e-6f * fabsf(Ar[n]) + 1e-30f);

    float h[DS];
    long ho = (long)((c * NB + b) * DI + d) * DS;
#pragma unroll
    for (int n = 0; n < DS; n++) h[n] = g_H[ho + n];

    const float Dd = Dp[d];
    const int base = ((b * DI + d) << 12) + t0;
    const float* dtp = g_dt + base;
    const float* up  = g_u  + base;
    const float* zp  = g_z  + base;
    float* yo = g_yout + base;

    for (int t = 0; t < CL; t++) {
        float dtv = dtp[t], uv = up[t];
        float du = dtv * uv;
        float y = 0.f;
        if (fast) {
            float r = __expf(dtv * Ar[0]);
            float a = r;
#pragma unroll
            for (int n = 0; n < DS; n++) {
                h[n] = fmaf(a, h[n], du * Bs[t][n]);
                y = fmaf(h[n], Cs[t][n], y);
                a *= r;
            }
        } else {
#pragma unroll
            for (int n = 0; n < DS; n++) {
                float aa = __expf(dtv * Ar[n]);
                h[n] = fmaf(aa, h[n], du * Bs[t][n]);
                y = fmaf(h[n], Cs[t][n], y);
            }
        }
        float zv = zp[t];
        float sz = zv / (1.f + __expf(-zv));
        yo[t] = (y + uv * Dd) * sz;
    }
}

// ---------------- 3x3 conv, cin split in 2 halves ----------------------------
__global__ void __launch_bounds__(256) conv3_kernel(const float* __restrict__ cw) {
    __shared__ float xs[4][34][36];
    __shared__ float ws[8][4][9];
    const int b = blockIdx.z;
    const int o0 = (blockIdx.y & 15) * 8;
    const int cs = blockIdx.y >> 4;
    const int cbase = cs * 128;
    const int ty0 = (blockIdx.x >> 1) * 32;
    const int tx0 = (blockIdx.x & 1) * 32;
    const int tid = threadIdx.x;
    const int py = (tid >> 4) << 1;
    const int px = (tid & 15) << 1;

    float acc[8][4];
#pragma unroll
    for (int o = 0; o < 8; o++)
#pragma unroll
        for (int p = 0; p < 4; p++) acc[o][p] = 0.f;

    for (int c0 = cbase; c0 < cbase + 128; c0 += 4) {
        for (int i = tid; i < 4 * 34 * 34; i += 256) {
            int cc = i / (34 * 34);
            int r = (i / 34) % 34;
            int col = i % 34;
            int gy = ty0 - 1 + r, gx = tx0 - 1 + col;
            float v = 0.f;
            if (gy >= 0 && gy < 64 && gx >= 0 && gx < 64)
                v = g_xr[((b * DM + c0 + cc) << 12) + (gy << 6) + gx];
            xs[cc][r][col] = v;
        }
        for (int i = tid; i < 288; i += 256) {
            int o = i / 36, rest = i % 36;
            int cc = rest / 9, k = rest % 9;
            ws[o][cc][k] = cw[((o0 + o) * 256 + c0 + cc) * 9 + k];
        }
        __syncthreads();
#pragma unroll
        for (int cc = 0; cc < 4; cc++) {
            float xv[4][4];
#pragma unroll
            for (int dy = 0; dy < 4; dy++)
#pragma unroll
                for (int dx = 0; dx < 4; dx++)
                    xv[dy][dx] = xs[cc][py + dy][px + dx];
#pragma unroll
            for (int o = 0; o < 8; o++) {
                float w[9];
#pragma unroll
                for (int k = 0; k < 9; k++) w[k] = ws[o][cc][k];
#pragma unroll
                for (int sy = 0; sy < 2; sy++)
#pragma unroll
                    for (int sx = 0; sx < 2; sx++) {
                        float s = acc[o][sy * 2 + sx];
#pragma unroll
                        for (int kh = 0; kh < 3; kh++)
#pragma unroll
                            for (int kw = 0; kw < 3; kw++)
                                s = fmaf(xv[sy + kh][sx + kw], w[kh * 3 + kw], s);
                        acc[o][sy * 2 + sx] = s;
                    }
            }
        }
        __syncthreads();
    }
#pragma unroll
    for (int o = 0; o < 8; o++) {
#pragma unroll
        for (int sy = 0; sy < 2; sy++)
#pragma unroll
            for (int sx = 0; sx < 2; sx++)
                g_y2s[cs][((b * 128 + o0 + o) << 12) + ((ty0 + py + sy) << 6) +
                          tx0 + px + sx] = acc[o][sy * 2 + sx];
    }
}

// ---------------- BN statistics per channel (bias cancels under BN) ----------
__global__ void bnstat_kernel() {
    __shared__ float ss[256], ss2[256];
    int ch = blockIdx.x;
    float s = 0.f, s2 = 0.f;
    for (int i = threadIdx.x; i < NB * L; i += 256) {
        int b = i >> 12, p = i & 4095;
        int off = ((b * 128 + ch) << 12) + p;
        float v = g_y2s[0][off] + g_y2s[1][off];
        s += v;
        s2 += v * v;
    }
    ss[threadIdx.x] = s;
    ss2[threadIdx.x] = s2;
    __syncthreads();
    for (int st = 128; st > 0; st >>= 1) {
        if (threadIdx.x < st) {
            ss[threadIdx.x] += ss[threadIdx.x + st];
            ss2[threadIdx.x] += ss2[threadIdx.x + st];
        }
        __syncthreads();
    }
    if (threadIdx.x == 0) {
        float inv = 1.f / (NB * L);
        float mean = ss[0] * inv;
        float var = ss2[0] * inv - mean * mean;
        g_mu[ch] = mean;
        g_rstd[ch] = rsqrtf(var + 1e-5f);
    }
}

// ---------------- BN apply + exact GELU, float4 ------------------------------
__global__ void bngelu_kernel(const float* __restrict__ gamma,
                              const float* __restrict__ beta,
                              float* __restrict__ out) {
    int i4 = blockIdx.x * 256 + threadIdx.x;
    if (i4 >= NB * 128 * (L / 4)) return;
    int ch = (i4 >> 10) & 127;
    float sc = g_rstd[ch] * gamma[ch];
    float sh = beta[ch] - g_mu[ch] * sc;
    float4 a = ((const float4*)g_y2s[0])[i4];
    float4 b = ((const float4*)g_y2s[1])[i4];
    float4 r;
    float v;
    v = fmaf(a.x + b.x, sc, sh); r.x = 0.5f * v * (1.f + erff(v * 0.70710678f));
    v = fmaf(a.y + b.y, sc, sh); r.y = 0.5f * v * (1.f + erff(v * 0.70710678f));
    v = fmaf(a.z + b.z, sc, sh); r.z = 0.5f * v * (1.f + erff(v * 0.70710678f));
    v = fmaf(a.w + b.w, sc, sh); r.w = 0.5f * v * (1.f + erff(v * 0.70710678f));
    ((float4*)out)[i4] = r;
}

// ---------------- launch ------------------------------------------------------
extern "C" void kernel_launch(void* const* d_in, const int* in_sizes, int n_in,
                              void* d_out, int out_size) {
    const float* x        = (const float*)d_in[0];
    const float* skip     = (const float*)d_in[1];
    const float* up_w     = (const float*)d_in[2];
    const float* up_b     = (const float*)d_in[3];
    const float* in_proj  = (const float*)d_in[4];
    const float* conv1d_w = (const float*)d_in[5];
    const float* conv1d_b = (const float*)d_in[6];
    const float* x_proj   = (const float*)d_in[7];
    const float* dt_proj  = (const float*)d_in[8];
    const float* dt_b     = (const float*)d_in[9];
    const float* A_log    = (const float*)d_in[10];
    const float* Dp       = (const float*)d_in[11];
    const float* out_proj = (const float*)d_in[12];
    const float* conv_w   = (const float*)d_in[13];
    const float* bn_g     = (const float*)d_in[15];
    const float* bn_b     = (const float*)d_in[16];
    float* out = (float*)d_out;

    prep_kernel<<<512, 256>>>(A_log, up_w);

    // upsample: M=1024, N=512, K=256
    gemm_kernel<0><<<dim3(8, 8, NB), 256>>>(x, nullptr, up_b, 512, 256, 1024,
                                            256 * 1024);
    skipcopy_kernel<<<1024, 256>>>(skip);

    // in_proj: M=4096, N=1024, K=256
    gemm_kernel<1><<<dim3(16, 32, NB), 256>>>(nullptr, in_proj, nullptr, 1024,
                                              256, L, DM * L);
    conv1d_kernel<<<(NB * DI * L / 4) / 256, 256>>>(conv1d_w, conv1d_b);

    // x_proj: M=4096, N=48, K=512
    gemm_kernel<2><<<dim3(1, 32, NB), 256>>>(nullptr, x_proj, nullptr, 48, DI,
                                             L, DI * L);
    // dt_proj: M=4096, N=512, K=16
    gemm_kernel<3><<<dim3(8, 32, NB), 256>>>(nullptr, dt_proj, dt_b, DI, 16, L,
                                             48 * L);

    scanA_kernel<<<dim3(4, NCH, NB), 128>>>();
    scanB_kernel<<<4, 256>>>();
    scanC_kernel<<<dim3(4, NCH, NB), 128>>>(Dp);

    // out_proj (+residual): M=4096, N=256, K=512
    gemm_kernel<4><<<dim3(4, 32, NB), 256>>>(nullptr, out_proj, nullptr, DM, DI,
                                             L, DI * L);

    conv3_kernel<<<dim3(4, 32, NB), 256>>>(conv_w);
    bnstat_kernel<<<128, 256>>>();
    bngelu_kernel<<<(NB * 128 * L / 4) / 256, 256>>>(bn_g, bn_b, out);
}